// round 9
// baseline (speedup 1.0000x reference)
#include <cuda_runtime.h>
#include <cstdint>

#define DIM      2048
#define NE       64
#define BK       32
#define MTILE    128
#define NTHREADS 256
#define LSTRIDE  65

// dynamic smem (floats): xs0[4096] xs1[4096] ws0[2112] ws1[2112] = 12416 floats
#define XS_FLOATS   4096
#define WS_FLOATS   2112
#define SMEM_FLOATS (2 * XS_FLOATS + 2 * WS_FLOATS)
#define SMEM_BYTES  (SMEM_FLOATS * 4)        // 49664

typedef unsigned long long u64;

__device__ __forceinline__ void ffma2(u64& d, u64 a, u64 b) {
    asm("fma.rn.f32x2 %0, %1, %2, %0;" : "+l"(d) : "l"(a), "l"(b));
}
__device__ __forceinline__ u64 pack2(float v) {
    u64 d; asm("mov.b64 %0, {%1, %1};" : "=l"(d) : "f"(v)); return d;
}

__global__ void __launch_bounds__(NTHREADS)
router_kernel(const float* __restrict__ x,
              const float* __restrict__ W,
              const float* __restrict__ bias,
              float* __restrict__ out,
              int out_size)
{
    extern __shared__ __align__(16) float raw[];
    float* xsb = raw;                    // two [32][128] swizzled buffers
    float* wsb = raw + 2 * XS_FLOATS;    // two [64][33] buffers

    const int tid = threadIdx.x;
    const int el  = tid & 15;            // expert lane: experts el, el+16, el+32, el+48
    const int t0  = (tid >> 4) * 8;      // tokens t0 .. t0+7
    const int kq  = tid & 7;             // fill: float4 index along k
    const int rr  = tid >> 3;            // fill: base row (0..31)
    const int blk = blockIdx.x;

    u64 acc[4][4];                       // 4 token-pairs x 4 experts
    #pragma unroll
    for (int p = 0; p < 4; p++)
        #pragma unroll
        for (int j = 0; j < 4; j++) acc[p][j] = 0ull;

    const float* xblk = x + (size_t)blk * MTILE * DIM;
    const int scol = 8 * (kq & 3);

    float4 px[4], pw[2];
    // ---- prefetch + store chunk 0 into buffer 0 ----
    #pragma unroll
    for (int i = 0; i < 4; i++)
        px[i] = *reinterpret_cast<const float4*>(&xblk[(size_t)(rr + 32 * i) * DIM + kq * 4]);
    #pragma unroll
    for (int i = 0; i < 2; i++)
        pw[i] = *reinterpret_cast<const float4*>(&W[(size_t)(rr + 32 * i) * DIM + kq * 4]);
    {
        float* xs = xsb; float* ws = wsb;
        #pragma unroll
        for (int i = 0; i < 4; i++) {
            const int col = (rr + 32 * i) ^ scol;
            xs[(4 * kq + 0) * 128 + col] = px[i].x;
            xs[(4 * kq + 1) * 128 + col] = px[i].y;
            xs[(4 * kq + 2) * 128 + col] = px[i].z;
            xs[(4 * kq + 3) * 128 + col] = px[i].w;
        }
        #pragma unroll
        for (int i = 0; i < 2; i++) {
            float* wrow = &ws[(rr + 32 * i) * 33 + kq * 4];
            wrow[0] = pw[i].x; wrow[1] = pw[i].y; wrow[2] = pw[i].z; wrow[3] = pw[i].w;
        }
    }

    const int NCHUNK = DIM / BK;         // 64
    for (int c = 0; c < NCHUNK; c++) {
        __syncthreads();                 // orders store(c) before compute(c), all warps

        // ---- prefetch chunk c+1 (lands during the 32-k compute) ----
        const int kn = (c + 1) * BK;
        if (kn < DIM) {
            #pragma unroll
            for (int i = 0; i < 4; i++)
                px[i] = *reinterpret_cast<const float4*>(
                    &xblk[(size_t)(rr + 32 * i) * DIM + kn + kq * 4]);
            #pragma unroll
            for (int i = 0; i < 2; i++)
                pw[i] = *reinterpret_cast<const float4*>(
                    &W[(size_t)(rr + 32 * i) * DIM + kn + kq * 4]);
        }

        const float* xs = xsb + (c & 1) * XS_FLOATS;
        const float* ws = wsb + (c & 1) * WS_FLOATS;

        // ---- compute: 32 k-steps, 16 FFMA2 each (8 tok x 4 exp) ----
        #pragma unroll 8
        for (int kk = 0; kk < BK; kk++) {
            const int col0 = t0 ^ (8 * ((kk >> 2) & 3));
            const ulonglong2 A0 = *reinterpret_cast<const ulonglong2*>(&xs[kk * 128 + col0]);
            const ulonglong2 A1 = *reinterpret_cast<const ulonglong2*>(&xs[kk * 128 + col0 + 4]);
            u64 a[4] = {A0.x, A0.y, A1.x, A1.y};

            u64 wd[4];
            #pragma unroll
            for (int j = 0; j < 4; j++) wd[j] = pack2(ws[(el + 16 * j) * 33 + kk]);
            #pragma unroll
            for (int p = 0; p < 4; p++)
                #pragma unroll
                for (int j = 0; j < 4; j++) ffma2(acc[p][j], a[p], wd[j]);
        }

        // ---- store chunk c+1 into the other buffer (safe: see sync proof) ----
        if (kn < DIM) {
            float* xs2 = xsb + ((c + 1) & 1) * XS_FLOATS;
            float* ws2 = wsb + ((c + 1) & 1) * WS_FLOATS;
            #pragma unroll
            for (int i = 0; i < 4; i++) {
                const int col = (rr + 32 * i) ^ scol;
                xs2[(4 * kq + 0) * 128 + col] = px[i].x;
                xs2[(4 * kq + 1) * 128 + col] = px[i].y;
                xs2[(4 * kq + 2) * 128 + col] = px[i].z;
                xs2[(4 * kq + 3) * 128 + col] = px[i].w;
            }
            #pragma unroll
            for (int i = 0; i < 2; i++) {
                float* wrow = &ws2[(rr + 32 * i) * 33 + kq * 4];
                wrow[0] = pw[i].x; wrow[1] = pw[i].y; wrow[2] = pw[i].z; wrow[3] = pw[i].w;
            }
        }
    }
    __syncthreads();

    // ---- logits (+bias) -> padded smem [token][LSTRIDE] ----
    float* lg = raw;
    #pragma unroll
    for (int j = 0; j < 4; j++) {
        const int e = el + 16 * j;
        const float be = __ldg(&bias[e]);
        #pragma unroll
        for (int p = 0; p < 4; p++) {
            const float lo = __uint_as_float((unsigned)(acc[p][j] & 0xffffffffull));
            const float hi = __uint_as_float((unsigned)(acc[p][j] >> 32));
            lg[(t0 + 2 * p)     * LSTRIDE + e] = lo + be;
            lg[(t0 + 2 * p + 1) * LSTRIDE + e] = hi + be;
        }
    }
    __syncthreads();

    // ---- per-token softmax + top-2 (threads 0..127) ----
    if (tid < MTILE) {
        const float* row = &lg[tid * LSTRIDE];
        float v1 = -3.402823466e38f, v2 = -3.402823466e38f;
        int   i1 = 0, i2 = 0;
        #pragma unroll
        for (int e = 0; e < NE; e++) {
            const float v = row[e];
            if (v > v1)      { v2 = v1; i2 = i1; v1 = v; i1 = e; }
            else if (v > v2) { v2 = v;  i2 = e; }
        }
        float sum = 0.0f;
        #pragma unroll
        for (int e = 0; e < NE; e++) sum += __expf(row[e] - v1);
        const float inv = 1.0f / sum;

        const int T    = blk * MTILE + tid;
        const int half = out_size >> 1;
        out[2 * T]            = (float)i1;
        out[2 * T + 1]        = (float)i2;
        out[half + 2 * T]     = inv;
        out[half + 2 * T + 1] = __expf(v2 - v1) * inv;
    }
}

extern "C" void kernel_launch(void* const* d_in, const int* in_sizes, int n_in,
                              void* d_out, int out_size) {
    const float* x = (const float*)d_in[0];
    const float* W = (const float*)d_in[1];
    const float* b = (const float*)d_in[2];
    cudaFuncSetAttribute(router_kernel,
                         cudaFuncAttributeMaxDynamicSharedMemorySize, SMEM_BYTES);
    router_kernel<<<128, NTHREADS, SMEM_BYTES>>>(x, W, b, (float*)d_out, out_size);
}

// round 10
// speedup vs baseline: 1.2844x; 1.2844x over previous
#include <cuda_runtime.h>
#include <cstdint>

#define DIM      2048
#define NE       64
#define BK       64
#define MTILE    128
#define NTHREADS 256
#define LSTRIDE  65

// dynamic smem: xs [64][128] f32 = 32768 B ; ws [64][65] u64 = 33280 B
#define XS_FLOATS  8192
#define SMEM_BYTES (32768 + 33280)   // 66048

typedef unsigned long long u64;

__device__ __forceinline__ void ffma2(u64& d, u64 a, u64 b) {
    asm("fma.rn.f32x2 %0, %1, %2, %0;" : "+l"(d) : "l"(a), "l"(b));
}
__device__ __forceinline__ u64 pack2(float v) {
    u64 d; asm("mov.b64 %0, {%1, %1};" : "=l"(d) : "f"(v)); return d;
}

__global__ void __launch_bounds__(NTHREADS)
router_kernel(const float* __restrict__ x,
              const float* __restrict__ W,
              const float* __restrict__ bias,
              float* __restrict__ out,
              int out_size)
{
    extern __shared__ __align__(16) float raw[];
    float* xs = raw;                           // [64][128] k-major, XOR-8 swizzled
    u64*   ws = (u64*)(raw + XS_FLOATS);       // [64][65] duplicated {w,w}

    const int tid = threadIdx.x;
    const int el  = tid & 15;            // expert lane: experts el, el+16, el+32, el+48
    const int t0  = (tid >> 4) * 8;      // tokens t0 .. t0+7
    const int kq  = tid & 7;             // x fill: quad pair (kq, kq+8)
    const int rr  = tid >> 3;            // x fill: base row (0..31)
    const int wq  = tid & 15;            // W fill: quad (0..15)
    const int wr  = tid >> 4;            // W fill: base expert row (0..15)
    const int blk = blockIdx.x;

    u64 acc[4][4];                       // 4 token-pairs x 4 experts
    #pragma unroll
    for (int p = 0; p < 4; p++)
        #pragma unroll
        for (int j = 0; j < 4; j++) acc[p][j] = 0ull;

    const float* xblk = x + (size_t)blk * MTILE * DIM;
    const int scol = 8 * (kq & 3);

    float4 px[8], pw[4];
    // ---- prefetch chunk 0 ----
    #pragma unroll
    for (int i = 0; i < 4; i++)
        #pragma unroll
        for (int h = 0; h < 2; h++)
            px[i * 2 + h] = *reinterpret_cast<const float4*>(
                &xblk[(size_t)(rr + 32 * i) * DIM + 4 * (kq + 8 * h)]);
    #pragma unroll
    for (int i = 0; i < 4; i++)
        pw[i] = *reinterpret_cast<const float4*>(&W[(size_t)(wr + 16 * i) * DIM + 4 * wq]);

    const int NCHUNK = DIM / BK;         // 32
    for (int c = 0; c < NCHUNK; c++) {
        // ---- store chunk c (consumes LDG issued before previous barrier) ----
        #pragma unroll
        for (int i = 0; i < 4; i++) {
            const int col = (rr + 32 * i) ^ scol;
            #pragma unroll
            for (int h = 0; h < 2; h++) {
                const int kb = 4 * (kq + 8 * h);
                const float4 v = px[i * 2 + h];
                xs[(kb + 0) * 128 + col] = v.x;
                xs[(kb + 1) * 128 + col] = v.y;
                xs[(kb + 2) * 128 + col] = v.z;
                xs[(kb + 3) * 128 + col] = v.w;
            }
        }
        #pragma unroll
        for (int i = 0; i < 4; i++) {
            u64* wrow = &ws[(wr + 16 * i) * 65 + 4 * wq];
            wrow[0] = pack2(pw[i].x);
            wrow[1] = pack2(pw[i].y);
            wrow[2] = pack2(pw[i].z);
            wrow[3] = pack2(pw[i].w);
        }
        __syncthreads();

        // ---- prefetch chunk c+1 (consumed only after the next barrier) ----
        const int kn = (c + 1) * BK;
        if (kn < DIM) {
            #pragma unroll
            for (int i = 0; i < 4; i++)
                #pragma unroll
                for (int h = 0; h < 2; h++)
                    px[i * 2 + h] = *reinterpret_cast<const float4*>(
                        &xblk[(size_t)(rr + 32 * i) * DIM + kn + 4 * (kq + 8 * h)]);
            #pragma unroll
            for (int i = 0; i < 4; i++)
                pw[i] = *reinterpret_cast<const float4*>(
                    &W[(size_t)(wr + 16 * i) * DIM + kn + 4 * wq]);
        }

        // ---- compute: 64 k-steps, 16 FFMA2 + 2 LDS.128 + 4 LDS.64 each ----
        #pragma unroll 8
        for (int kk = 0; kk < BK; kk++) {
            const int col0 = t0 ^ (8 * ((kk >> 2) & 3));
            const ulonglong2 A0 = *reinterpret_cast<const ulonglong2*>(&xs[kk * 128 + col0]);
            const ulonglong2 A1 = *reinterpret_cast<const ulonglong2*>(&xs[kk * 128 + col0 + 4]);
            u64 a[4] = {A0.x, A0.y, A1.x, A1.y};

            u64 wd[4];
            #pragma unroll
            for (int j = 0; j < 4; j++) wd[j] = ws[(el + 16 * j) * 65 + kk];
            #pragma unroll
            for (int p = 0; p < 4; p++)
                #pragma unroll
                for (int j = 0; j < 4; j++) ffma2(acc[p][j], a[p], wd[j]);
        }
        __syncthreads();
    }

    // ---- logits (+bias) -> padded smem [token][LSTRIDE] ----
    float* lg = raw;
    #pragma unroll
    for (int j = 0; j < 4; j++) {
        const int e = el + 16 * j;
        const float be = __ldg(&bias[e]);
        #pragma unroll
        for (int p = 0; p < 4; p++) {
            const float lo = __uint_as_float((unsigned)(acc[p][j] & 0xffffffffull));
            const float hi = __uint_as_float((unsigned)(acc[p][j] >> 32));
            lg[(t0 + 2 * p)     * LSTRIDE + e] = lo + be;
            lg[(t0 + 2 * p + 1) * LSTRIDE + e] = hi + be;
        }
    }
    __syncthreads();

    // ---- per-token softmax + top-2 (threads 0..127) ----
    if (tid < MTILE) {
        const float* row = &lg[tid * LSTRIDE];
        float v1 = -3.402823466e38f, v2 = -3.402823466e38f;
        int   i1 = 0, i2 = 0;
        #pragma unroll
        for (int e = 0; e < NE; e++) {
            const float v = row[e];
            if (v > v1)      { v2 = v1; i2 = i1; v1 = v; i1 = e; }
            else if (v > v2) { v2 = v;  i2 = e; }
        }
        float sum = 0.0f;
        #pragma unroll
        for (int e = 0; e < NE; e++) sum += __expf(row[e] - v1);
        const float inv = 1.0f / sum;

        const int T    = blk * MTILE + tid;
        const int half = out_size >> 1;
        out[2 * T]            = (float)i1;
        out[2 * T + 1]        = (float)i2;
        out[half + 2 * T]     = inv;
        out[half + 2 * T + 1] = __expf(v2 - v1) * inv;
    }
}

extern "C" void kernel_launch(void* const* d_in, const int* in_sizes, int n_in,
                              void* d_out, int out_size) {
    const float* x = (const float*)d_in[0];
    const float* W = (const float*)d_in[1];
    const float* b = (const float*)d_in[2];
    cudaFuncSetAttribute(router_kernel,
                         cudaFuncAttributeMaxDynamicSharedMemorySize, SMEM_BYTES);
    router_kernel<<<128, NTHREADS, SMEM_BYTES>>>(x, W, b, (float*)d_out, out_size);
}

// round 12
// speedup vs baseline: 1.4603x; 1.1369x over previous
#include <cuda_runtime.h>
#include <cstdint>

#define DIM      2048
#define NE       64
#define BK       64
#define MTILE    128
#define NTHREADS 256
#define LSTRIDE  65

// dynamic smem: xs [64][128] f32 = 32768 B ; ws [64][65] f32 = 16640 B
#define XS_FLOATS  8192
#define SMEM_BYTES (32768 + 16640)   // 49408

typedef unsigned long long u64;

__device__ __forceinline__ void ffma2(u64& d, u64 a, u64 b) {
    asm("fma.rn.f32x2 %0, %1, %2, %0;" : "+l"(d) : "l"(a), "l"(b));
}
__device__ __forceinline__ u64 pack2(float v) {
    u64 d; asm("mov.b64 %0, {%1, %1};" : "=l"(d) : "f"(v)); return d;
}

__global__ void __launch_bounds__(NTHREADS)
router_kernel(const float* __restrict__ x,
              const float* __restrict__ W,
              const float* __restrict__ bias,
              float* __restrict__ out,
              int out_size)
{
    extern __shared__ __align__(16) float raw[];
    float* xs = raw;                     // [64][128] k-major, XOR-8 swizzled
    float* ws = raw + XS_FLOATS;         // [64][65] expert-major f32

    const int tid = threadIdx.x;
    const int el  = tid & 15;            // expert lane: experts el, el+16, el+32, el+48
    const int t0  = (tid >> 4) * 8;      // tokens t0 .. t0+7
    const int kq  = tid & 7;             // x fill: quad pair (kq, kq+8)
    const int rr  = tid >> 3;            // x fill: base row (0..31)
    const int we  = tid & 63;            // W fill: expert row
    const int wq  = tid >> 6;            // W fill: base quad (0..3)
    const int blk = blockIdx.x;

    u64 acc[4][4];                       // 4 token-pairs x 4 experts
    #pragma unroll
    for (int p = 0; p < 4; p++)
        #pragma unroll
        for (int j = 0; j < 4; j++) acc[p][j] = 0ull;

    const float* xblk = x + (size_t)blk * MTILE * DIM;
    const int scol = 8 * (kq & 3);

    float4 px[8], pw[4];
    // ---- prefetch chunk 0 ----
    #pragma unroll
    for (int i = 0; i < 4; i++)
        #pragma unroll
        for (int h = 0; h < 2; h++)
            px[i * 2 + h] = *reinterpret_cast<const float4*>(
                &xblk[(size_t)(rr + 32 * i) * DIM + 4 * (kq + 8 * h)]);
    #pragma unroll
    for (int i = 0; i < 4; i++)
        pw[i] = *reinterpret_cast<const float4*>(&W[(size_t)we * DIM + 4 * (wq + 4 * i)]);

    const int NCHUNK = DIM / BK;         // 32
    for (int c = 0; c < NCHUNK; c++) {
        // ---- store chunk c (LDG for it was issued before previous barrier) ----
        #pragma unroll
        for (int i = 0; i < 4; i++) {
            const int col = (rr + 32 * i) ^ scol;
            #pragma unroll
            for (int h = 0; h < 2; h++) {
                const int kb = 4 * (kq + 8 * h);
                const float4 v = px[i * 2 + h];
                xs[(kb + 0) * 128 + col] = v.x;
                xs[(kb + 1) * 128 + col] = v.y;
                xs[(kb + 2) * 128 + col] = v.z;
                xs[(kb + 3) * 128 + col] = v.w;
            }
        }
        #pragma unroll
        for (int i = 0; i < 4; i++) {
            float* wrow = &ws[we * 65 + 4 * (wq + 4 * i)];   // 4B-aligned: scalar stores only
            wrow[0] = pw[i].x; wrow[1] = pw[i].y; wrow[2] = pw[i].z; wrow[3] = pw[i].w;
        }
        __syncthreads();

        // ---- prefetch chunk c+1 (consumed only after the next barrier) ----
        const int kn = (c + 1) * BK;
        if (kn < DIM) {
            #pragma unroll
            for (int i = 0; i < 4; i++)
                #pragma unroll
                for (int h = 0; h < 2; h++)
                    px[i * 2 + h] = *reinterpret_cast<const float4*>(
                        &xblk[(size_t)(rr + 32 * i) * DIM + kn + 4 * (kq + 8 * h)]);
            #pragma unroll
            for (int i = 0; i < 4; i++)
                pw[i] = *reinterpret_cast<const float4*>(
                    &W[(size_t)we * DIM + kn + 4 * (wq + 4 * i)]);
        }

        // ---- compute: 64 k-steps, R7 mainloop (16 FFMA2 + 2 LDS.128 + 4 LDS.32) ----
        #pragma unroll 8
        for (int kk = 0; kk < BK; kk++) {
            const int col0 = t0 ^ (8 * ((kk >> 2) & 3));
            const ulonglong2 A0 = *reinterpret_cast<const ulonglong2*>(&xs[kk * 128 + col0]);
            const ulonglong2 A1 = *reinterpret_cast<const ulonglong2*>(&xs[kk * 128 + col0 + 4]);
            u64 a[4] = {A0.x, A0.y, A1.x, A1.y};

            u64 wd[4];
            #pragma unroll
            for (int j = 0; j < 4; j++) wd[j] = pack2(ws[(el + 16 * j) * 65 + kk]);
            #pragma unroll
            for (int p = 0; p < 4; p++)
                #pragma unroll
                for (int j = 0; j < 4; j++) ffma2(acc[p][j], a[p], wd[j]);
        }
        __syncthreads();
    }

    // ---- logits (+bias) -> padded smem [token][LSTRIDE] ----
    float* lg = raw;
    #pragma unroll
    for (int j = 0; j < 4; j++) {
        const int e = el + 16 * j;
        const float be = __ldg(&bias[e]);
        #pragma unroll
        for (int p = 0; p < 4; p++) {
            const float lo = __uint_as_float((unsigned)(acc[p][j] & 0xffffffffull));
            const float hi = __uint_as_float((unsigned)(acc[p][j] >> 32));
            lg[(t0 + 2 * p)     * LSTRIDE + e] = lo + be;
            lg[(t0 + 2 * p + 1) * LSTRIDE + e] = hi + be;
        }
    }
    __syncthreads();

    // ---- per-token softmax + top-2 (threads 0..127) ----
    if (tid < MTILE) {
        const float* row = &lg[tid * LSTRIDE];
        float v1 = -3.402823466e38f, v2 = -3.402823466e38f;
        int   i1 = 0, i2 = 0;
        #pragma unroll
        for (int e = 0; e < NE; e++) {
            const float v = row[e];
            if (v > v1)      { v2 = v1; i2 = i1; v1 = v; i1 = e; }
            else if (v > v2) { v2 = v;  i2 = e; }
        }
        float sum = 0.0f;
        #pragma unroll
        for (int e = 0; e < NE; e++) sum += __expf(row[e] - v1);
        const float inv = 1.0f / sum;

        const int T    = blk * MTILE + tid;
        const int half = out_size >> 1;
        out[2 * T]            = (float)i1;
        out[2 * T + 1]        = (float)i2;
        out[half + 2 * T]     = inv;
        out[half + 2 * T + 1] = __expf(v2 - v1) * inv;
    }
}

extern "C" void kernel_launch(void* const* d_in, const int* in_sizes, int n_in,
                              void* d_out, int out_size) {
    const float* x = (const float*)d_in[0];
    const float* W = (const float*)d_in[1];
    const float* b = (const float*)d_in[2];
    cudaFuncSetAttribute(router_kernel,
                         cudaFuncAttributeMaxDynamicSharedMemorySize, SMEM_BYTES);
    router_kernel<<<128, NTHREADS, SMEM_BYTES>>>(x, W, b, (float*)d_out, out_size);
}